// round 13
// baseline (speedup 1.0000x reference)
#include <cuda_runtime.h>
#include <cstdint>

// LinearRationalSpline forward, sm_103a — R11.
// R6 pipeline shape (TILES=4, grid 2048, 2-deep double buffer) but staging
// only w+h (32 floats/row) via 4B cp.async -> smem 64.5KB -> 33.8KB,
// 3 -> 6 blocks/SM. d/lam become traffic-neutral LDG gathers inside the
// compute phase.

#define NBINS 16
#define ROWP  63                    // 4*NBINS - 1
#define TPB   128
#define SMSTRIDE 33
#define TILE_SM (TPB * SMSTRIDE)    // 4224 floats per buffer
#define TILES_PER_BLOCK 4
#define BOUNDV 3.0f
#define MBW 0.001f
#define MBH 0.001f
#define MDRV 0.001f
#define MLAM 0.025f
#define EPSV 1e-6f

__device__ __forceinline__ float softplus_f(float v) {
    return fmaxf(v, 0.0f) + log1pf(__expf(-fabsf(v)));
}

// stage w+h (first 32 floats) of 128 rows; warp-coalesced 4B cp.async.
__device__ __forceinline__ void stage_tile(float* __restrict__ sbuf,
                                           const float* __restrict__ params,
                                           long long tile, int tid) {
    const int warp = tid >> 5;
    const int lane = tid & 31;
    const long long rowBase = tile * TPB;
    #pragma unroll
    for (int i = 0; i < 32; i++) {
        const int r = i * 4 + warp;
        const float* src = params + (rowBase + r) * ROWP + lane;
        unsigned sa = (unsigned)__cvta_generic_to_shared(sbuf + r * SMSTRIDE + lane);
        asm volatile("cp.async.ca.shared.global [%0], [%1], 4;\n" :: "r"(sa), "l"(src));
    }
}

__global__ __launch_bounds__(TPB, 6)
void lrs_kernel(const float* __restrict__ inputs,
                const float* __restrict__ params,
                float* __restrict__ out,
                int n) {
    extern __shared__ float sm[];   // 2 * 4224 floats = 33792 B

    const int tid = threadIdx.x;
    const long long t0 = (long long)blockIdx.x * TILES_PER_BLOCK;

    // prologue: prefetch tiles t0, t0+1
    stage_tile(sm,           params, t0,     tid);
    asm volatile("cp.async.commit_group;\n");
    stage_tile(sm + TILE_SM, params, t0 + 1, tid);
    asm volatile("cp.async.commit_group;\n");

    #pragma unroll
    for (int k = 0; k < TILES_PER_BLOCK; k++) {
        const long long tile = t0 + k;
        const int gid = (int)tile * TPB + tid;
        const float x = inputs[gid];          // issue before waiting

        if (k == TILES_PER_BLOCK - 1) asm volatile("cp.async.wait_group 0;\n");
        else                          asm volatile("cp.async.wait_group 1;\n");
        __syncthreads();

        const float* __restrict__ row = sm + (k & 1) * TILE_SM + tid * SMSTRIDE;
        const long long rbase = (long long)gid * ROWP;

        // ---------------- softmax exps ----------------
        float we[NBINS], he[NBINS];
        float sw = 0.0f, sh = 0.0f;
        #pragma unroll
        for (int i = 0; i < NBINS; i++) { we[i] = __expf(row[i]);         sw += we[i]; }
        #pragma unroll
        for (int i = 0; i < NBINS; i++) { he[i] = __expf(row[NBINS + i]); sh += he[i]; }
        const float wscale = (1.0f - MBW * (float)NBINS) * __fdividef(1.0f, sw);
        const float hscale = (1.0f - MBH * (float)NBINS) * __fdividef(1.0f, sh);

        // ---------- fused knot pass: pred_j == (j <= idx) ----------
        float cumw = 0.0f, cumh = 0.0f;
        float klo = -BOUNDV, hlo = -BOUNDV, khi = BOUNDV, hhi = BOUNDV;
        bool prevp = true;
        int idx = 0;
        #pragma unroll
        for (int j = 1; j <= NBINS; j++) {
            cumw += fmaf(wscale, we[j - 1], MBW);
            cumh += fmaf(hscale, he[j - 1], MBH);
            const float wkn = (j == NBINS) ? BOUNDV : fmaf(6.0f, cumw, -BOUNDV);
            const float hkn = (j == NBINS) ? BOUNDV : fmaf(6.0f, cumh, -BOUNDV);
            const bool pred = (j < NBINS) && ((wkn + EPSV) <= x);
            if (pred) { klo = wkn; hlo = hkn; idx++; }
            const bool take = prevp && !pred;      // j == idx+1
            if (take) { khi = wkn; hhi = hkn; }
            prevp = pred;
        }

        // ---- data-dependent gathers (traffic-neutral; fill DRAM duty) ----
        const int i0 = (idx > 0)         ? (2 * NBINS + idx - 1) : 2 * NBINS;
        const int i1 = (idx < NBINS - 1) ? (2 * NBINS + idx)     : (3 * NBINS - 2);
        const float d0raw = params[rbase + i0];
        const float d1raw = params[rbase + i1];
        const float lraw  = params[rbase + 3 * NBINS - 1 + idx];

        const float cw   = klo;
        const float wsel = khi - klo;
        const float ch   = hlo;
        const float hsel = hhi - hlo;

        const float EDGE = 1.0f - MDRV;
        const float d0 = (idx == 0)         ? EDGE : (MDRV + softplus_f(d0raw));
        const float d1 = (idx == NBINS - 1) ? EDGE : (MDRV + softplus_f(d1raw));
        const float sig = __fdividef(1.0f, 1.0f + __expf(-lraw));
        const float lam = fmaf(1.0f - 2.0f * MLAM, sig, MLAM);

        // ---------------- rational spline ----------------
        const float delta = __fdividef(hsel, wsel);
        const float wb  = sqrtf(__fdividef(d0, d1));
        const float lwb = lam * wb;
        const float wc  = __fdividef(lam * d0 + (wb - lwb) * d1, delta);
        const float ya  = ch;
        const float yb  = ch + hsel;
        const float l1  = 1.0f - lam;
        const float yc  = __fdividef(lwb * yb + l1 * ya, l1 + lwb);

        const float theta = __fdividef(x - cw, wsel);
        const bool  ind   = theta <= lam;
        const float lt    = lam - theta;

        const float wcyc      = wc * yc;
        const float wcyctheta = wcyc * theta;
        const float num = ind ? (wcyctheta + ya * lt)
                              : ((wcyc - wcyctheta) - wb * yb * lt);
        const float wctheta = wc * theta;
        const float den = ind ? (wctheta + lt)
                              : ((wc - wctheta) - wb * lt);

        float outv = __fdividef(num, den);
        const float dnum = __fdividef(wc * (ind ? lam * (yc - ya)
                                               : (wb - lwb) * (yb - yc)), wsel);
        float lad = __logf(dnum) - 2.0f * __logf(fabsf(den));

        const bool outside = (x < -BOUNDV) || (x > BOUNDV);
        if (outside) { outv = x; lad = 0.0f; }

        out[gid]     = outv;
        out[n + gid] = lad;

        // refill the buffer we just consumed with tile k+2
        if (k < TILES_PER_BLOCK - 2) {
            __syncthreads();                       // all readers of buf (k&1) done
            stage_tile(sm + (k & 1) * TILE_SM, params, t0 + k + 2, tid);
            asm volatile("cp.async.commit_group;\n");
        }
    }
}

extern "C" void kernel_launch(void* const* d_in, const int* in_sizes, int n_in,
                              void* d_out, int out_size) {
    const float* inputs = (const float*)d_in[0];
    const float* params = (const float*)d_in[1];
    float* out = (float*)d_out;
    const int n = in_sizes[0];                       // 1,048,576
    const int smem = 2 * TILE_SM * sizeof(float);    // 33792
    cudaFuncSetAttribute(lrs_kernel, cudaFuncAttributeMaxDynamicSharedMemorySize, smem);
    const int blocks = (n / TPB) / TILES_PER_BLOCK;  // 2048
    lrs_kernel<<<blocks, TPB, smem>>>(inputs, params, out, n);
}

// round 16
// speedup vs baseline: 1.6310x; 1.6310x over previous
#include <cuda_runtime.h>
#include <cstdint>

// LinearRationalSpline forward, sm_103a — R14.
// Champion R6 pipeline (full-row 16B cp.async staging, 2-deep double buffer,
// TILES=4) with tile granularity halved: TPB=64, 64-row tiles, grid 4096.
// Same 12 warps/SM but 6 independent block pipelines per SM -> fill/drain/
// tail bubbles halved. Access pattern identical to R6 (the only one that
// sustains >5.7 TB/s).

#define NBINS 16
#define ROWP  63                    // 4*NBINS - 1
#define TPB   64
#define TILE_FLOATS (TPB * ROWP)    // 4032
#define F4_PER_TILE (TILE_FLOATS / 4)  // 1008 = 15*64 + 48
#define TILES_PER_BLOCK 4
#define BOUNDV 3.0f
#define MBW 0.001f
#define MBH 0.001f
#define MDRV 0.001f
#define MLAM 0.025f
#define EPSV 1e-6f

__device__ __forceinline__ float softplus_f(float v) {
    return fmaxf(v, 0.0f) + log1pf(__expf(-fabsf(v)));
}

__device__ __forceinline__ void stage_tile(float* __restrict__ sbuf,
                                           const float* __restrict__ params,
                                           long long tile, int tid) {
    const float4* __restrict__ g4 =
        reinterpret_cast<const float4*>(params) + tile * F4_PER_TILE;
    float4* s4 = reinterpret_cast<float4*>(sbuf);
    #pragma unroll
    for (int i = 0; i < 15; i++) {
        unsigned sa = (unsigned)__cvta_generic_to_shared(s4 + i * TPB + tid);
        asm volatile("cp.async.cg.shared.global [%0], [%1], 16;\n"
                     :: "r"(sa), "l"(g4 + i * TPB + tid));
    }
    if (tid < 48) {
        unsigned sa = (unsigned)__cvta_generic_to_shared(s4 + 15 * TPB + tid);
        asm volatile("cp.async.cg.shared.global [%0], [%1], 16;\n"
                     :: "r"(sa), "l"(g4 + 15 * TPB + tid));
    }
}

__global__ __launch_bounds__(TPB)
void lrs_kernel(const float* __restrict__ inputs,
                const float* __restrict__ params,
                float* __restrict__ out,
                int n) {
    extern __shared__ float sm[];   // 2 * 4032 floats = 32256 B

    const int tid = threadIdx.x;
    const long long t0 = (long long)blockIdx.x * TILES_PER_BLOCK;

    // prologue: prefetch tiles t0, t0+1
    stage_tile(sm,               params, t0,     tid);
    asm volatile("cp.async.commit_group;\n");
    stage_tile(sm + TILE_FLOATS, params, t0 + 1, tid);
    asm volatile("cp.async.commit_group;\n");

    #pragma unroll
    for (int k = 0; k < TILES_PER_BLOCK; k++) {
        const long long tile = t0 + k;
        const int gid = (int)tile * TPB + tid;
        const float x = inputs[gid];          // issue before waiting

        if (k == TILES_PER_BLOCK - 1) asm volatile("cp.async.wait_group 0;\n");
        else                          asm volatile("cp.async.wait_group 1;\n");
        __syncthreads();

        const float* __restrict__ row = sm + (k & 1) * TILE_FLOATS + tid * ROWP;

        // ---------------- softmax exps ----------------
        float we[NBINS], he[NBINS];
        float sw = 0.0f, sh = 0.0f;
        #pragma unroll
        for (int i = 0; i < NBINS; i++) { we[i] = __expf(row[i]);         sw += we[i]; }
        #pragma unroll
        for (int i = 0; i < NBINS; i++) { he[i] = __expf(row[NBINS + i]); sh += he[i]; }
        const float wscale = (1.0f - MBW * (float)NBINS) * __fdividef(1.0f, sw);
        const float hscale = (1.0f - MBH * (float)NBINS) * __fdividef(1.0f, sh);

        // ---------- fused knot pass: pred_j == (j <= idx) ----------
        float cumw = 0.0f, cumh = 0.0f;
        float klo = -BOUNDV, hlo = -BOUNDV, khi = BOUNDV, hhi = BOUNDV;
        bool prevp = true;
        int idx = 0;
        #pragma unroll
        for (int j = 1; j <= NBINS; j++) {
            cumw += fmaf(wscale, we[j - 1], MBW);
            cumh += fmaf(hscale, he[j - 1], MBH);
            const float wkn = (j == NBINS) ? BOUNDV : fmaf(6.0f, cumw, -BOUNDV);
            const float hkn = (j == NBINS) ? BOUNDV : fmaf(6.0f, cumh, -BOUNDV);
            const bool pred = (j < NBINS) && ((wkn + EPSV) <= x);
            if (pred) { klo = wkn; hlo = hkn; idx++; }
            const bool take = prevp && !pred;      // j == idx+1
            if (take) { khi = wkn; hhi = hkn; }
            prevp = pred;
        }

        const float cw   = klo;
        const float wsel = khi - klo;
        const float ch   = hlo;
        const float hsel = hhi - hlo;

        // ---------- derivatives + lambda (from staged smem row) ----------
        const float EDGE = 1.0f - MDRV;
        const float d0 = (idx == 0)         ? EDGE
                         : (MDRV + softplus_f(row[2 * NBINS + idx - 1]));
        const float d1 = (idx == NBINS - 1) ? EDGE
                         : (MDRV + softplus_f(row[2 * NBINS + idx]));
        const float lraw = row[3 * NBINS - 1 + idx];
        const float sig  = __fdividef(1.0f, 1.0f + __expf(-lraw));
        const float lam  = fmaf(1.0f - 2.0f * MLAM, sig, MLAM);

        // ---------------- rational spline ----------------
        const float delta = __fdividef(hsel, wsel);
        const float wb  = sqrtf(__fdividef(d0, d1));
        const float lwb = lam * wb;
        const float wc  = __fdividef(lam * d0 + (wb - lwb) * d1, delta);
        const float ya  = ch;
        const float yb  = ch + hsel;
        const float l1  = 1.0f - lam;
        const float yc  = __fdividef(lwb * yb + l1 * ya, l1 + lwb);

        const float theta = __fdividef(x - cw, wsel);
        const bool  ind   = theta <= lam;
        const float lt    = lam - theta;

        const float wcyc      = wc * yc;
        const float wcyctheta = wcyc * theta;
        const float num = ind ? (wcyctheta + ya * lt)
                              : ((wcyc - wcyctheta) - wb * yb * lt);
        const float wctheta = wc * theta;
        const float den = ind ? (wctheta + lt)
                              : ((wc - wctheta) - wb * lt);

        float outv = __fdividef(num, den);
        const float dnum = __fdividef(wc * (ind ? lam * (yc - ya)
                                               : (wb - lwb) * (yb - yc)), wsel);
        float lad = __logf(dnum) - 2.0f * __logf(fabsf(den));

        const bool outside = (x < -BOUNDV) || (x > BOUNDV);
        if (outside) { outv = x; lad = 0.0f; }

        out[gid]     = outv;
        out[n + gid] = lad;

        // refill the buffer we just consumed with tile k+2
        if (k < TILES_PER_BLOCK - 2) {
            __syncthreads();                       // all readers of buf (k&1) done
            stage_tile(sm + (k & 1) * TILE_FLOATS, params, t0 + k + 2, tid);
            asm volatile("cp.async.commit_group;\n");
        }
    }
}

extern "C" void kernel_launch(void* const* d_in, const int* in_sizes, int n_in,
                              void* d_out, int out_size) {
    const float* inputs = (const float*)d_in[0];
    const float* params = (const float*)d_in[1];
    float* out = (float*)d_out;
    const int n = in_sizes[0];                       // 1,048,576
    const int smem = 2 * TILE_FLOATS * sizeof(float);  // 32256
    cudaFuncSetAttribute(lrs_kernel, cudaFuncAttributeMaxDynamicSharedMemorySize, smem);
    const int blocks = (n / TPB) / TILES_PER_BLOCK;  // 4096
    lrs_kernel<<<blocks, TPB, smem>>>(inputs, params, out, n);
}